// round 2
// baseline (speedup 1.0000x reference)
#include <cuda_runtime.h>
#include <cuda_bf16.h>

// BitGatConv — algebraic collapse.
//
// reference:  coefs = softmax(scores, axis=1)            # over j
//             vals  = sum_j coefs[i,j,c] * nhs[i,c]      # nhs broadcast over j
// => vals[i,c] = nhs[i,c] * sum_j coefs[i,j,c] = nhs[i,c] * 1
// (every row has a self-loop, masked entries underflow to exactly 0 in exp)
//
// So the output is exactly nhs = nodes_ft @ weight : [1536,256] @ [256,64].
// conv_weight1/2 and adj_bias_mat are dead inputs.

#define NROWS   1536
#define KDIM    256
#define HCDIM   64
#define ROWS_PER_BLK 8
#define THREADS 128   // 8 rows x 16 col-quads

__global__ __launch_bounds__(THREADS)
void bitgat_nhs_kernel(const float* __restrict__ nodes_ft,
                       const float* __restrict__ weight,
                       float* __restrict__ out)
{
    // Stage this block's 8x256 slice of nodes_ft in shared memory (8 KB).
    __shared__ float4 s_nf[ROWS_PER_BLK * KDIM / 4];   // 512 float4

    const int tid  = threadIdx.x;
    const int row0 = blockIdx.x * ROWS_PER_BLK;

    const float4* src = reinterpret_cast<const float4*>(nodes_ft + (size_t)row0 * KDIM);
    #pragma unroll
    for (int i = tid; i < ROWS_PER_BLK * KDIM / 4; i += THREADS)
        s_nf[i] = src[i];
    __syncthreads();

    const int r  = tid >> 4;     // 0..7   row within block
    const int cq = tid & 15;     // 0..15  column quad (c = 4*cq)

    // weight viewed as float4: element [k][cq] at index k*16 + cq
    const float4* __restrict__ wq = reinterpret_cast<const float4*>(weight);
    const float4* __restrict__ a  = &s_nf[r * (KDIM / 4)];

    float4 acc = make_float4(0.f, 0.f, 0.f, 0.f);

    #pragma unroll 8
    for (int k4 = 0; k4 < KDIM / 4; ++k4) {
        const float4 av = a[k4];                         // broadcast LDS.128
        const float4 w0 = wq[(4 * k4 + 0) * 16 + cq];    // LDG.128, L1-resident
        const float4 w1 = wq[(4 * k4 + 1) * 16 + cq];
        const float4 w2 = wq[(4 * k4 + 2) * 16 + cq];
        const float4 w3 = wq[(4 * k4 + 3) * 16 + cq];

        acc.x = fmaf(av.x, w0.x, acc.x);
        acc.y = fmaf(av.x, w0.y, acc.y);
        acc.z = fmaf(av.x, w0.z, acc.z);
        acc.w = fmaf(av.x, w0.w, acc.w);

        acc.x = fmaf(av.y, w1.x, acc.x);
        acc.y = fmaf(av.y, w1.y, acc.y);
        acc.z = fmaf(av.y, w1.z, acc.z);
        acc.w = fmaf(av.y, w1.w, acc.w);

        acc.x = fmaf(av.z, w2.x, acc.x);
        acc.y = fmaf(av.z, w2.y, acc.y);
        acc.z = fmaf(av.z, w2.z, acc.z);
        acc.w = fmaf(av.z, w2.w, acc.w);

        acc.x = fmaf(av.w, w3.x, acc.x);
        acc.y = fmaf(av.w, w3.y, acc.y);
        acc.z = fmaf(av.w, w3.z, acc.z);
        acc.w = fmaf(av.w, w3.w, acc.w);
    }

    float4* dst = reinterpret_cast<float4*>(out + (size_t)(row0 + r) * HCDIM);
    dst[cq] = acc;   // STG.128
}

extern "C" void kernel_launch(void* const* d_in, const int* in_sizes, int n_in,
                              void* d_out, int out_size)
{
    // metadata order: nodes_ft, adj_bias_mat, weight, conv_weight1, conv_weight2
    const float* nodes_ft = (const float*)d_in[0];
    const float* weight   = (const float*)d_in[2];
    float* out = (float*)d_out;

    (void)in_sizes; (void)n_in; (void)out_size;

    bitgat_nhs_kernel<<<NROWS / ROWS_PER_BLK, THREADS>>>(nodes_ft, weight, out);
}

// round 4
// speedup vs baseline: 1.4129x; 1.4129x over previous
#include <cuda_runtime.h>
#include <cuda_bf16.h>

// BitGatConv — algebraic collapse (verified R1, rel_err 6.6e-8):
//   vals[i,c] = nhs[i,c] * sum_j softmax(...)[i,j,c] = nhs[i,c]
// => out = nodes_ft @ weight  : [1536,256] @ [256,64]
//
// R2: weight staged in SMEM (2 K-phases x 32KB) so the inner loop is
// LDS-only (29cyc fixed-lat) instead of L2-latency-bound LDG (~250cyc).

#define NROWS   1536
#define KDIM    256
#define HCDIM   64
#define ROWS_PER_BLK 8
#define THREADS 128           // 8 rows x 16 col-quads
#define KPHASE  128           // K per phase
#define WQ_PER_PHASE (KPHASE * (HCDIM / 4))   // 2048 float4 = 32 KB

__global__ __launch_bounds__(THREADS)
void bitgat_nhs_kernel(const float* __restrict__ nodes_ft,
                       const float* __restrict__ weight,
                       float* __restrict__ out)
{
    __shared__ float4 s_w[WQ_PER_PHASE];               // 32 KB weight half
    __shared__ float4 s_nf[ROWS_PER_BLK * KDIM / 4];   // 8 KB node tile

    const int tid  = threadIdx.x;
    const int row0 = blockIdx.x * ROWS_PER_BLK;

    const float4* __restrict__ wq  = reinterpret_cast<const float4*>(weight);
    const float4* __restrict__ src = reinterpret_cast<const float4*>(nodes_ft + (size_t)row0 * KDIM);

    const int r  = tid >> 4;     // 0..7  row within block
    const int cq = tid & 15;     // 0..15 column quad

    float4 acc = make_float4(0.f, 0.f, 0.f, 0.f);

    // ---- phase 0: stage nodes tile + first weight half ----
    #pragma unroll
    for (int i = 0; i < (ROWS_PER_BLK * KDIM / 4) / THREADS; ++i)
        s_nf[tid + i * THREADS] = src[tid + i * THREADS];
    #pragma unroll
    for (int i = 0; i < WQ_PER_PHASE / THREADS; ++i)        // 16 independent LDG.128
        s_w[tid + i * THREADS] = wq[tid + i * THREADS];
    __syncthreads();

    #pragma unroll
    for (int phase = 0; phase < KDIM / KPHASE; ++phase) {
        if (phase > 0) {
            __syncthreads();   // drain readers before overwrite
            #pragma unroll
            for (int i = 0; i < WQ_PER_PHASE / THREADS; ++i)
                s_w[tid + i * THREADS] = wq[phase * WQ_PER_PHASE + tid + i * THREADS];
            __syncthreads();
        }

        const float4* __restrict__ a = &s_nf[r * (KDIM / 4) + phase * (KPHASE / 4)];

        #pragma unroll 4
        for (int k4 = 0; k4 < KPHASE / 4; ++k4) {
            const float4 av = a[k4];                       // LDS.128 broadcast
            const float4 w0 = s_w[(4 * k4 + 0) * 16 + cq]; // LDS.128 conflict-free
            const float4 w1 = s_w[(4 * k4 + 1) * 16 + cq];
            const float4 w2 = s_w[(4 * k4 + 2) * 16 + cq];
            const float4 w3 = s_w[(4 * k4 + 3) * 16 + cq];

            acc.x = fmaf(av.x, w0.x, acc.x);
            acc.y = fmaf(av.x, w0.y, acc.y);
            acc.z = fmaf(av.x, w0.z, acc.z);
            acc.w = fmaf(av.x, w0.w, acc.w);

            acc.x = fmaf(av.y, w1.x, acc.x);
            acc.y = fmaf(av.y, w1.y, acc.y);
            acc.z = fmaf(av.y, w1.z, acc.z);
            acc.w = fmaf(av.y, w1.w, acc.w);

            acc.x = fmaf(av.z, w2.x, acc.x);
            acc.y = fmaf(av.z, w2.y, acc.y);
            acc.z = fmaf(av.z, w2.z, acc.z);
            acc.w = fmaf(av.z, w2.w, acc.w);

            acc.x = fmaf(av.w, w3.x, acc.x);
            acc.y = fmaf(av.w, w3.y, acc.y);
            acc.z = fmaf(av.w, w3.z, acc.z);
            acc.w = fmaf(av.w, w3.w, acc.w);
        }
    }

    float4* dst = reinterpret_cast<float4*>(out + (size_t)(row0 + r) * HCDIM);
    dst[cq] = acc;   // STG.128
}

extern "C" void kernel_launch(void* const* d_in, const int* in_sizes, int n_in,
                              void* d_out, int out_size)
{
    // metadata order: nodes_ft, adj_bias_mat, weight, conv_weight1, conv_weight2
    const float* nodes_ft = (const float*)d_in[0];
    const float* weight   = (const float*)d_in[2];
    float* out = (float*)d_out;

    (void)in_sizes; (void)n_in; (void)out_size;

    bitgat_nhs_kernel<<<NROWS / ROWS_PER_BLK, THREADS>>>(nodes_ft, weight, out);
}

// round 6
// speedup vs baseline: 1.6215x; 1.1477x over previous
#include <cuda_runtime.h>
#include <cuda_bf16.h>

// BitGatConv — algebraic collapse (verified R1/R2, rel_err 6.6e-8):
//   vals[i,c] = nhs[i,c] * sum_j softmax(...)[i,j,c] = nhs[i,c]
// => out = nodes_ft @ weight  : [1536,256] @ [256,64]
//
// R4: single-wave grid (128 blocks x 12 rows) + in-block split-K x2
// (384 threads = 12 warps/block, 1536 warps chip-wide) to hide LDS latency.

#define NROWS        1536
#define KDIM         256
#define HCDIM        64
#define ROWS_PER_BLK 12
#define GRID         (NROWS / ROWS_PER_BLK)      // 128
#define KSPLIT       2
#define THREADS      (ROWS_PER_BLK * 16 * KSPLIT) // 384
#define KPHASE       128                          // K per weight phase
#define WQ_PER_PHASE (KPHASE * (HCDIM / 4))       // 2048 float4 = 32 KB
#define NF_Q         (ROWS_PER_BLK * KDIM / 4)    // 768  float4 = 12 KB

__global__ __launch_bounds__(THREADS)
void bitgat_nhs_kernel(const float* __restrict__ nodes_ft,
                       const float* __restrict__ weight,
                       float* __restrict__ out)
{
    __shared__ float4 s_w[WQ_PER_PHASE];          // 32 KB  weight phase
    __shared__ float4 s_nf[NF_Q];                 // 12 KB  node tile
    __shared__ float4 s_red[ROWS_PER_BLK * 16];   //  3 KB  split-K reduce

    const int tid  = threadIdx.x;
    const int row0 = blockIdx.x * ROWS_PER_BLK;

    const int kh  = tid / (ROWS_PER_BLK * 16);    // 0/1  K-half
    const int rem = tid % (ROWS_PER_BLK * 16);
    const int r   = rem >> 4;                     // 0..11 row
    const int cq  = rem & 15;                     // 0..15 col quad

    const float4* __restrict__ wq  = reinterpret_cast<const float4*>(weight);
    const float4* __restrict__ src = reinterpret_cast<const float4*>(nodes_ft + (size_t)row0 * KDIM);

    float4 acc = make_float4(0.f, 0.f, 0.f, 0.f);

    // ---- stage node tile (768 float4, 2 per thread) + weight phase 0 ----
    #pragma unroll
    for (int i = tid; i < NF_Q; i += THREADS)
        s_nf[i] = src[i];
    #pragma unroll
    for (int i = tid; i < WQ_PER_PHASE; i += THREADS)
        s_w[i] = wq[i];
    __syncthreads();

    #pragma unroll
    for (int phase = 0; phase < KDIM / KPHASE; ++phase) {
        if (phase > 0) {
            __syncthreads();     // drain readers before overwrite
            #pragma unroll
            for (int i = tid; i < WQ_PER_PHASE; i += THREADS)
                s_w[i] = wq[phase * WQ_PER_PHASE + i];
            __syncthreads();
        }

        // this thread's k4 range within the phase: [kh*16, kh*16+16)
        const float4* __restrict__ a = &s_nf[r * (KDIM / 4) + phase * (KPHASE / 4) + kh * 16];
        const float4* __restrict__ w = &s_w[kh * 16 * 4 * 16];

        #pragma unroll 4
        for (int k4 = 0; k4 < 16; ++k4) {
            const float4 av = a[k4];                      // LDS.128 broadcast
            const float4 w0 = w[(4 * k4 + 0) * 16 + cq];  // LDS.128 conflict-free
            const float4 w1 = w[(4 * k4 + 1) * 16 + cq];
            const float4 w2 = w[(4 * k4 + 2) * 16 + cq];
            const float4 w3 = w[(4 * k4 + 3) * 16 + cq];

            acc.x = fmaf(av.x, w0.x, acc.x);
            acc.y = fmaf(av.x, w0.y, acc.y);
            acc.z = fmaf(av.x, w0.z, acc.z);
            acc.w = fmaf(av.x, w0.w, acc.w);

            acc.x = fmaf(av.y, w1.x, acc.x);
            acc.y = fmaf(av.y, w1.y, acc.y);
            acc.z = fmaf(av.y, w1.z, acc.z);
            acc.w = fmaf(av.y, w1.w, acc.w);

            acc.x = fmaf(av.z, w2.x, acc.x);
            acc.y = fmaf(av.z, w2.y, acc.y);
            acc.z = fmaf(av.z, w2.z, acc.z);
            acc.w = fmaf(av.z, w2.w, acc.w);

            acc.x = fmaf(av.w, w3.x, acc.x);
            acc.y = fmaf(av.w, w3.y, acc.y);
            acc.z = fmaf(av.w, w3.z, acc.z);
            acc.w = fmaf(av.w, w3.w, acc.w);
        }
    }

    // ---- split-K reduction: kh=1 publishes, kh=0 combines + stores ----
    __syncthreads();
    if (kh == 1)
        s_red[rem] = acc;
    __syncthreads();
    if (kh == 0) {
        const float4 p = s_red[rem];
        acc.x += p.x; acc.y += p.y; acc.z += p.z; acc.w += p.w;
        float4* dst = reinterpret_cast<float4*>(out + (size_t)(row0 + r) * HCDIM);
        dst[cq] = acc;   // STG.128
    }
}

extern "C" void kernel_launch(void* const* d_in, const int* in_sizes, int n_in,
                              void* d_out, int out_size)
{
    // metadata order: nodes_ft, adj_bias_mat, weight, conv_weight1, conv_weight2
    const float* nodes_ft = (const float*)d_in[0];
    const float* weight   = (const float*)d_in[2];
    float* out = (float*)d_out;

    (void)in_sizes; (void)n_in; (void)out_size;

    bitgat_nhs_kernel<<<GRID, THREADS>>>(nodes_ft, weight, out);
}